// round 1
// baseline (speedup 1.0000x reference)
#include <cuda_runtime.h>
#include <cstdint>

#define NN 50000
#define RR 33
#define DD 1600
#define WSZ 16
#define CC 10
#define NRW 528   // R*WS
#define NRC 330   // R*C

// Scratch (static device globals; allocation is forbidden)
__device__ float g_proj1[(size_t)NN * NRW];   // 105.6 MB
__device__ float g_h1[NN * WSZ];              // 3.2 MB
__device__ float g_h2[(size_t)NN * NRC];      // 66 MB

__device__ __forceinline__ unsigned f2tf(float x) {
    unsigned u; asm("cvt.rna.tf32.f32 %0, %1;" : "=r"(u) : "f"(x)); return u;
}

__device__ __forceinline__ void mma8(float* d, const unsigned* a, const unsigned* b) {
    asm volatile("mma.sync.aligned.m16n8k8.row.col.f32.tf32.tf32.f32 "
                 "{%0,%1,%2,%3}, {%4,%5,%6,%7}, {%8,%9}, {%0,%1,%2,%3};\n"
                 : "+f"(d[0]), "+f"(d[1]), "+f"(d[2]), "+f"(d[3])
                 : "r"(a[0]), "r"(a[1]), "r"(a[2]), "r"(a[3]),
                   "r"(b[0]), "r"(b[1]));
}

// ---------------- GEMM1: proj1[N,528] = emb[N,1600] @ W1cat ----------------
#define BM 128
#define BN 96      // 528 padded to 576 -> 6 n-tiles
#define BK 16
#define AST 20     // smem A stride (floats): (g*20+tg) distinct mod 32
#define BST 104    // smem B stride: (tg*8+g) distinct mod 32

__global__ __launch_bounds__(256) void k_gemm1(const float* __restrict__ emb,
                                               const float* __restrict__ w1) {
    __shared__ float sA[2][BM * AST];
    __shared__ float sB[2][BK * BST];
    const int tid = threadIdx.x;
    const int row0 = blockIdx.y * BM;
    const int col0 = blockIdx.x * BN;
    const int warp = tid >> 5, lane = tid & 31;
    const int g = lane >> 2, tg = lane & 3;
    const int wm = warp & 1, wn = warp >> 1;   // 2 x 4 warp grid, warp tile 64x24

    const int am = tid >> 2;        // 0..63 (2 passes of 64 rows)
    const int ak = (tid & 3) * 4;   // 0,4,8,12

    float acc[4][3][4];
    #pragma unroll
    for (int i = 0; i < 4; i++)
        #pragma unroll
        for (int j = 0; j < 3; j++)
            #pragma unroll
            for (int q = 0; q < 4; q++) acc[i][j][q] = 0.f;

    float4 ra[2];
    float rb[6];

    // prologue: global->reg for tile 0
    {
        #pragma unroll
        for (int p = 0; p < 2; p++) {
            int grow = row0 + am + p * 64;
            ra[p] = (grow < NN) ? *(const float4*)(emb + (size_t)grow * DD + ak)
                                : make_float4(0.f, 0.f, 0.f, 0.f);
        }
        #pragma unroll
        for (int i = 0; i < 6; i++) {
            int e = tid + 256 * i;
            int d = e / BN, j = e - d * BN;
            int jg = col0 + j;
            float v = 0.f;
            if (jg < NRW) {
                int p = jg >> 4, w = jg & 15;
                v = w1[p * (DD * WSZ) + d * WSZ + w];
            }
            rb[i] = v;
        }
    }
    // reg->smem buf 0 (convert to tf32 once here)
    {
        #pragma unroll
        for (int p = 0; p < 2; p++) {
            int m = am + p * 64;
            uint4 u = make_uint4(f2tf(ra[p].x), f2tf(ra[p].y), f2tf(ra[p].z), f2tf(ra[p].w));
            *(uint4*)&sA[0][m * AST + ak] = u;
        }
        #pragma unroll
        for (int i = 0; i < 6; i++) {
            int e = tid + 256 * i;
            int d = e / BN, j = e - d * BN;
            sB[0][d * BST + j] = __uint_as_float(f2tf(rb[i]));
        }
    }
    __syncthreads();

    const int T = DD / BK;  // 100
    for (int t = 0; t < T; t++) {
        const int cur = t & 1;
        if (t + 1 < T) {
            const int k0 = (t + 1) * BK;
            #pragma unroll
            for (int p = 0; p < 2; p++) {
                int grow = row0 + am + p * 64;
                ra[p] = (grow < NN) ? *(const float4*)(emb + (size_t)grow * DD + k0 + ak)
                                    : make_float4(0.f, 0.f, 0.f, 0.f);
            }
            #pragma unroll
            for (int i = 0; i < 6; i++) {
                int e = tid + 256 * i;
                int d = e / BN, j = e - d * BN;
                int jg = col0 + j;
                float v = 0.f;
                if (jg < NRW) {
                    int p = jg >> 4, w = jg & 15;
                    v = w1[p * (DD * WSZ) + (k0 + d) * WSZ + w];
                }
                rb[i] = v;
            }
        }
        // compute current buffer: 2 k8 steps
        #pragma unroll
        for (int s = 0; s < 2; s++) {
            unsigned af[4][4], bf[3][2];
            const int kc = s * 8 + tg;
            #pragma unroll
            for (int mi = 0; mi < 4; mi++) {
                int mrow = wm * 64 + mi * 16 + g;
                af[mi][0] = __float_as_uint(sA[cur][mrow * AST + kc]);
                af[mi][1] = __float_as_uint(sA[cur][(mrow + 8) * AST + kc]);
                af[mi][2] = __float_as_uint(sA[cur][mrow * AST + kc + 4]);
                af[mi][3] = __float_as_uint(sA[cur][(mrow + 8) * AST + kc + 4]);
            }
            #pragma unroll
            for (int ni = 0; ni < 3; ni++) {
                int ncol = wn * 24 + ni * 8 + g;
                bf[ni][0] = __float_as_uint(sB[cur][kc * BST + ncol]);
                bf[ni][1] = __float_as_uint(sB[cur][(kc + 4) * BST + ncol]);
            }
            #pragma unroll
            for (int mi = 0; mi < 4; mi++)
                #pragma unroll
                for (int ni = 0; ni < 3; ni++)
                    mma8(acc[mi][ni], af[mi], bf[ni]);
        }
        if (t + 1 < T) {
            const int nxt = cur ^ 1;
            #pragma unroll
            for (int p = 0; p < 2; p++) {
                int m = am + p * 64;
                uint4 u = make_uint4(f2tf(ra[p].x), f2tf(ra[p].y), f2tf(ra[p].z), f2tf(ra[p].w));
                *(uint4*)&sA[nxt][m * AST + ak] = u;
            }
            #pragma unroll
            for (int i = 0; i < 6; i++) {
                int e = tid + 256 * i;
                int d = e / BN, j = e - d * BN;
                sB[nxt][d * BST + j] = __uint_as_float(f2tf(rb[i]));
            }
        }
        __syncthreads();
    }

    // epilogue
    #pragma unroll
    for (int mi = 0; mi < 4; mi++) {
        #pragma unroll
        for (int ni = 0; ni < 3; ni++) {
            int r = row0 + wm * 64 + mi * 16 + g;
            int c = col0 + wn * 24 + ni * 8 + 2 * tg;
            if (c < NRW) {
                if (r < NN)
                    *(float2*)&g_proj1[(size_t)r * NRW + c] =
                        make_float2(acc[mi][ni][0], acc[mi][ni][1]);
                if (r + 8 < NN)
                    *(float2*)&g_proj1[(size_t)(r + 8) * NRW + c] =
                        make_float2(acc[mi][ni][2], acc[mi][ni][3]);
            }
        }
    }
}

// ---------------- init kernels ----------------
__global__ void k_zero_h1() {
    int i = blockIdx.x * blockDim.x + threadIdx.x;
    if (i < NN * WSZ) g_h1[i] = 0.f;
}

__global__ void k_init_out(float* __restrict__ out, const float* __restrict__ b2) {
    int i = blockIdx.x * blockDim.x + threadIdx.x;
    if (i < NN * CC) out[i] = b2[i % CC];
}

// ---------------- edge aggregation 1: h1[s] += val * proj1[o, p*16 : +16] ----------------
__global__ void k_edge1(const float* __restrict__ ev, const int* __restrict__ es,
                        const int* __restrict__ ep, const int* __restrict__ eo, int E) {
    int idx = blockIdx.x * blockDim.x + threadIdx.x;
    int e = idx >> 2;
    if (e >= E) return;
    int q = idx & 3;
    int s = es[e], p = ep[e], o = eo[e];
    float v = ev[e];
    // 64B-aligned contiguous gather (528*4 = 33*64)
    float4 m = *(const float4*)(g_proj1 + (size_t)o * NRW + p * WSZ + q * 4);
    float* dst = g_h1 + s * WSZ + q * 4;
    atomicAdd(dst + 0, v * m.x);
    atomicAdd(dst + 1, v * m.y);
    atomicAdd(dst + 2, v * m.z);
    atomicAdd(dst + 3, v * m.w);
}

// ---------------- layer2 projection: h2[n,330] = relu(h1[n]+b1) @ W2cat ----------------
__global__ __launch_bounds__(256) void k_proj2(const float* __restrict__ b1,
                                               const float* __restrict__ w2) {
    __shared__ float sw[WSZ * 336];  // [w][j], stride 336 -> conflict-free lane reads
    int tid = threadIdx.x;
    for (int u = tid; u < NRC * WSZ; u += 256) {
        int w = u / NRC, j = u - w * NRC;
        sw[w * 336 + j] = w2[(j / CC) * (WSZ * CC) + w * CC + (j % CC)];
    }
    __syncthreads();
    int warp = tid >> 5, lane = tid & 31;
    int rowbase = (blockIdx.x * 8 + warp) * 8;
    for (int r = 0; r < 8; r++) {
        int row = rowbase + r;
        if (row >= NN) return;
        float mv = 0.f;
        if (lane < WSZ) {
            mv = g_h1[row * WSZ + lane] + b1[lane];
            mv = fmaxf(mv, 0.f);
        }
        float h[16];
        #pragma unroll
        for (int w = 0; w < 16; w++) h[w] = __shfl_sync(0xffffffffu, mv, w);
        #pragma unroll
        for (int i = 0; i < 11; i++) {
            int j = i * 32 + lane;
            if (j < NRC) {
                float a = 0.f;
                #pragma unroll
                for (int w = 0; w < 16; w++) a += h[w] * sw[w * 336 + j];
                g_h2[(size_t)row * NRC + j] = a;
            }
        }
    }
}

// ---------------- edge aggregation 2: out[s] += val * h2[o, p*10 : +10] ----------------
__global__ void k_edge2(const float* __restrict__ ev, const int* __restrict__ es,
                        const int* __restrict__ ep, const int* __restrict__ eo,
                        float* __restrict__ out, int E) {
    int e = blockIdx.x * blockDim.x + threadIdx.x;
    if (e >= E) return;
    int s = es[e], p = ep[e], o = eo[e];
    float v = ev[e];
    const float* src = g_h2 + (size_t)o * NRC + p * CC;
    float* dst = out + s * CC;
    #pragma unroll
    for (int i = 0; i < 5; i++) {
        float2 m = *(const float2*)(src + i * 2);  // 8B aligned: 330*4 and 10*4 are mult of 8
        atomicAdd(dst + i * 2, v * m.x);
        atomicAdd(dst + i * 2 + 1, v * m.y);
    }
}

// ---------------- launch ----------------
extern "C" void kernel_launch(void* const* d_in, const int* in_sizes, int n_in,
                              void* d_out, int out_size) {
    const float* emb = (const float*)d_in[0];
    const float* w1  = (const float*)d_in[1];
    const float* b1  = (const float*)d_in[2];
    const float* w2  = (const float*)d_in[3];
    const float* b2  = (const float*)d_in[4];
    const float* ev  = (const float*)d_in[5];
    const int*   es  = (const int*)d_in[6];
    const int*   ep  = (const int*)d_in[7];
    const int*   eo  = (const int*)d_in[8];
    float* out = (float*)d_out;
    const int E = in_sizes[5];

    k_zero_h1<<<(NN * WSZ + 255) / 256, 256>>>();
    k_gemm1<<<dim3(6, (NN + BM - 1) / BM), 256>>>(emb, w1);
    k_edge1<<<((long long)E * 4 + 255) / 256, 256>>>(ev, es, ep, eo, E);
    k_proj2<<<(NN + 63) / 64, 256>>>(b1, w2);
    k_init_out<<<(NN * CC + 255) / 256, 256>>>(out, b2);
    k_edge2<<<(E + 255) / 256, 256>>>(ev, es, ep, eo, out, E);
}

// round 5
// speedup vs baseline: 1.4902x; 1.4902x over previous
#include <cuda_runtime.h>
#include <cuda_fp16.h>
#include <cstdint>

#define NN 50000
#define RR 33
#define DD 1600
#define WSZ 16
#define CC 10
#define NRW 528
#define NRC 330
#define NRWP 576   // padded cols for GEMM (6 tiles of 96)

// ---- scratch (static device globals; allocation forbidden) ----
__device__ __half g_proj1[(size_t)NN * NRW];   // 52.8 MB (L2-resident)
__device__ float  g_h1[NN * WSZ];              // 3.2 MB
__device__ float  g_a1[NN * WSZ];              // 3.2 MB
__device__ __half g_h2[(size_t)NN * NRC];      // 33 MB
__device__ __half g_w1t[(size_t)NRWP * DD];    // 1.84 MB, [j][d] transposed fp16, zero-padded

__device__ __forceinline__ uint32_t smem_u32(const void* p) {
    uint32_t a;
    asm("{ .reg .u64 t; cvta.to.shared.u64 t, %1; cvt.u32.u64 %0, t; }" : "=r"(a) : "l"(p));
    return a;
}
__device__ __forceinline__ uint32_t pk_h2(float a, float b) {
    __half2 h = __floats2half2_rn(a, b);
    return *reinterpret_cast<uint32_t*>(&h);
}
__device__ __forceinline__ float2 upk_h2(uint32_t u) {
    __half2 h = *reinterpret_cast<__half2*>(&u);
    return __half22float2(h);
}

__device__ __forceinline__ void mma16816(float* d, const unsigned* a, const unsigned* b) {
    asm volatile("mma.sync.aligned.m16n8k16.row.col.f32.f16.f16.f32 "
                 "{%0,%1,%2,%3}, {%4,%5,%6,%7}, {%8,%9}, {%0,%1,%2,%3};\n"
                 : "+f"(d[0]), "+f"(d[1]), "+f"(d[2]), "+f"(d[3])
                 : "r"(a[0]), "r"(a[1]), "r"(a[2]), "r"(a[3]),
                   "r"(b[0]), "r"(b[1]));
}
__device__ __forceinline__ void ldsm_x4(unsigned* r, uint32_t addr) {
    asm volatile("ldmatrix.sync.aligned.m8n8.x4.shared.b16 {%0,%1,%2,%3}, [%4];"
                 : "=r"(r[0]), "=r"(r[1]), "=r"(r[2]), "=r"(r[3]) : "r"(addr));
}

// ============================ prep: w1 transpose->fp16, zero h1, init out ============================
__global__ void k_prep(const float* __restrict__ w1, const float* __restrict__ b2,
                       float* __restrict__ out) {
    int i = blockIdx.x * blockDim.x + threadIdx.x;
    if (i < NRWP * DD) {
        int j = i / DD, d = i - j * DD;
        float x = 0.f;
        if (j < NRW) x = w1[(j >> 4) * (DD * WSZ) + d * WSZ + (j & 15)];
        g_w1t[i] = __float2half_rn(x);
    }
    if (i < NN * WSZ) g_h1[i] = 0.f;
    if (i < NN * CC) out[i] = b2[i % CC];
}

// ============================ GEMM1: proj1[N,528](fp16) = emb[N,1600] @ W1cat ============================
// BM=128, BN=96, BK=32, 256 threads, 2x4 warp grid (warp tile 64x24), fp16 m16n8k16.
// smem row stride 80B -> conflict-free ldmatrix (bank base 20r mod 32 is a permutation).
#define ASTR 80
#define ABYTES (128 * ASTR)   // 10240
#define BBYTES (96 * ASTR)    // 7680

__global__ __launch_bounds__(256) void k_gemm1(const float* __restrict__ emb) {
    __shared__ __align__(16) char sA[2][ABYTES];
    __shared__ __align__(16) char sB[2][BBYTES];

    const int tid = threadIdx.x;
    const int warp = tid >> 5, lane = tid & 31;
    const int g = lane >> 2, tg = lane & 3;
    const int wm = warp & 1, wn = warp >> 1;
    const int row0 = blockIdx.y * 128;
    const int col0 = blockIdx.x * 96;

    const int arow = tid >> 1, ahalf = tid & 1;           // A fill: 16 floats each
    const int grow = row0 + arow;
    const bool aok = grow < NN;
    const float* asrc0 = emb + (size_t)grow * DD + ahalf * 16;

    const int br0 = tid >> 2, bc0 = tid & 3;              // B fill chunk 0 (rows 0..63)
    const int br1 = (tid + 256) >> 2;                     // chunk 1 (rows 64..95, tid<128)
    const __half* bsrc0 = g_w1t + (size_t)(col0 + br0) * DD + bc0 * 8;
    const __half* bsrc1 = g_w1t + (size_t)(col0 + br1) * DD + bc0 * 8;

    float acc[4][3][4];
    #pragma unroll
    for (int i = 0; i < 4; i++)
        #pragma unroll
        for (int j = 0; j < 3; j++)
            #pragma unroll
            for (int q = 0; q < 4; q++) acc[i][j][q] = 0.f;

    float4 pa[4];
    uint4 pb0, pb1;

    // ---- prologue: prefetch k0=0 ----
    #pragma unroll
    for (int u = 0; u < 4; u++)
        pa[u] = aok ? *(const float4*)(asrc0 + u * 4) : make_float4(0, 0, 0, 0);
    pb0 = *(const uint4*)bsrc0;
    if (tid < 128) pb1 = *(const uint4*)bsrc1;

    // store buf 0
    {
        uint4 u0, u1;
        u0.x = pk_h2(pa[0].x, pa[0].y); u0.y = pk_h2(pa[0].z, pa[0].w);
        u0.z = pk_h2(pa[1].x, pa[1].y); u0.w = pk_h2(pa[1].z, pa[1].w);
        u1.x = pk_h2(pa[2].x, pa[2].y); u1.y = pk_h2(pa[2].z, pa[2].w);
        u1.z = pk_h2(pa[3].x, pa[3].y); u1.w = pk_h2(pa[3].z, pa[3].w);
        char* d = sA[0] + arow * ASTR + ahalf * 32;
        *(uint4*)d = u0; *(uint4*)(d + 16) = u1;
        *(uint4*)(sB[0] + br0 * ASTR + bc0 * 16) = pb0;
        if (tid < 128) *(uint4*)(sB[0] + br1 * ASTR + bc0 * 16) = pb1;
    }
    __syncthreads();

    // per-warp smem read base for ldmatrix (A)
    const uint32_t aBase0 = smem_u32(sA[0]) + (wm * 64 + (lane & 15)) * ASTR + (lane >> 4) * 16;

    const int T = DD / 32;  // 50
    for (int t = 0; t < T; t++) {
        const int cur = t & 1;
        if (t + 1 < T) {
            const int k0 = (t + 1) * 32;
            #pragma unroll
            for (int u = 0; u < 4; u++)
                pa[u] = aok ? *(const float4*)(asrc0 + k0 + u * 4) : make_float4(0, 0, 0, 0);
            pb0 = *(const uint4*)(bsrc0 + k0);
            if (tid < 128) pb1 = *(const uint4*)(bsrc1 + k0);
        }

        const uint32_t aB = aBase0 + cur * ABYTES;
        #pragma unroll
        for (int s = 0; s < 2; s++) {
            unsigned af[4][4], bf[3][2];
            #pragma unroll
            for (int mi = 0; mi < 4; mi++)
                ldsm_x4(af[mi], aB + mi * (16 * ASTR) + s * 32);
            // B fragment loads (plain LDS.32; conflict-free)
            #pragma unroll
            for (int ni = 0; ni < 3; ni++) {
                const char* p = (const char*)sB[cur] + (wn * 24 + ni * 8 + g) * ASTR + s * 32 + tg * 4;
                bf[ni][0] = *(const unsigned*)p;
                bf[ni][1] = *(const unsigned*)(p + 16);
            }
            #pragma unroll
            for (int mi = 0; mi < 4; mi++)
                #pragma unroll
                for (int ni = 0; ni < 3; ni++)
                    mma16816(acc[mi][ni], af[mi], bf[ni]);
        }

        if (t + 1 < T) {
            const int nxt = cur ^ 1;
            uint4 u0, u1;
            u0.x = pk_h2(pa[0].x, pa[0].y); u0.y = pk_h2(pa[0].z, pa[0].w);
            u0.z = pk_h2(pa[1].x, pa[1].y); u0.w = pk_h2(pa[1].z, pa[1].w);
            u1.x = pk_h2(pa[2].x, pa[2].y); u1.y = pk_h2(pa[2].z, pa[2].w);
            u1.z = pk_h2(pa[3].x, pa[3].y); u1.w = pk_h2(pa[3].z, pa[3].w);
            char* d = sA[nxt] + arow * ASTR + ahalf * 32;
            *(uint4*)d = u0; *(uint4*)(d + 16) = u1;
            *(uint4*)(sB[nxt] + br0 * ASTR + bc0 * 16) = pb0;
            if (tid < 128) *(uint4*)(sB[nxt] + br1 * ASTR + bc0 * 16) = pb1;
        }
        __syncthreads();
    }

    // ---- epilogue: fp32 acc -> fp16 proj1 ----
    #pragma unroll
    for (int mi = 0; mi < 4; mi++) {
        #pragma unroll
        for (int ni = 0; ni < 3; ni++) {
            int r = row0 + wm * 64 + mi * 16 + g;
            int c = col0 + wn * 24 + ni * 8 + 2 * tg;
            if (c < NRW) {
                if (r < NN)
                    *(uint32_t*)&g_proj1[(size_t)r * NRW + c] = pk_h2(acc[mi][ni][0], acc[mi][ni][1]);
                if (r + 8 < NN)
                    *(uint32_t*)&g_proj1[(size_t)(r + 8) * NRW + c] = pk_h2(acc[mi][ni][2], acc[mi][ni][3]);
            }
        }
    }
}

// ============================ edge aggregation 1 ============================
// h1[s] += val * proj1[o, p*16 : +16]  (2 threads/edge, fp16 gather, v4 vector red)
__global__ void k_edge1(const float* __restrict__ ev, const int* __restrict__ es,
                        const int* __restrict__ ep, const int* __restrict__ eo, int E) {
    int idx = blockIdx.x * blockDim.x + threadIdx.x;
    int e = idx >> 1;
    if (e >= E) return;
    int q = idx & 1;
    int s = es[e], p = ep[e], o = eo[e];
    float v = ev[e];
    const uint4 m = *(const uint4*)(g_proj1 + (size_t)o * NRW + p * WSZ + q * 8);
    float2 f0 = upk_h2(m.x), f1 = upk_h2(m.y), f2 = upk_h2(m.z), f3 = upk_h2(m.w);
    float* dst = g_h1 + s * WSZ + q * 8;
    asm volatile("red.global.add.v4.f32 [%0], {%1,%2,%3,%4};"
                 :: "l"(dst), "f"(v * f0.x), "f"(v * f0.y), "f"(v * f1.x), "f"(v * f1.y) : "memory");
    asm volatile("red.global.add.v4.f32 [%0], {%1,%2,%3,%4};"
                 :: "l"(dst + 4), "f"(v * f2.x), "f"(v * f2.y), "f"(v * f3.x), "f"(v * f3.y) : "memory");
}

// ============================ bias1 + relu ============================
__global__ void k_act(const float* __restrict__ b1) {
    int i = blockIdx.x * blockDim.x + threadIdx.x;
    if (i < NN * WSZ) g_a1[i] = fmaxf(g_h1[i] + b1[i & 15], 0.f);
}

// ============================ layer-2 projection ============================
// h2[n, j](fp16) = sum_w a1[n,w] * w2[j/10, w, j%10]; one col/thread, weights in regs
__global__ __launch_bounds__(128) void k_proj2(const float* __restrict__ w2) {
    int j = blockIdx.y * 128 + threadIdx.x;
    if (j >= NRC) return;
    int p = j / CC, c = j - p * CC;
    float wr[WSZ];
    #pragma unroll
    for (int w = 0; w < WSZ; w++) wr[w] = w2[p * (WSZ * CC) + w * CC + c];
    int r0 = blockIdx.x * 256;
    int r1 = min(r0 + 256, NN);
    for (int row = r0; row < r1; row++) {
        const float4* hp = (const float4*)(g_a1 + row * WSZ);
        float4 a0 = __ldg(hp), a1v = __ldg(hp + 1), a2 = __ldg(hp + 2), a3 = __ldg(hp + 3);
        float acc = a0.x * wr[0] + a0.y * wr[1] + a0.z * wr[2] + a0.w * wr[3]
                  + a1v.x * wr[4] + a1v.y * wr[5] + a1v.z * wr[6] + a1v.w * wr[7]
                  + a2.x * wr[8] + a2.y * wr[9] + a2.z * wr[10] + a2.w * wr[11]
                  + a3.x * wr[12] + a3.y * wr[13] + a3.z * wr[14] + a3.w * wr[15];
        g_h2[(size_t)row * NRC + j] = __float2half_rn(acc);
    }
}

// ============================ edge aggregation 2 ============================
// out[s] += val * h2[o, p*10 : +10]  (1 thread/edge, v2 vector red)
__global__ void k_edge2(const float* __restrict__ ev, const int* __restrict__ es,
                        const int* __restrict__ ep, const int* __restrict__ eo,
                        float* __restrict__ out, int E) {
    int e = blockIdx.x * blockDim.x + threadIdx.x;
    if (e >= E) return;
    int s = es[e], p = ep[e], o = eo[e];
    float v = ev[e];
    const uint32_t* src = (const uint32_t*)(g_h2 + (size_t)o * NRC + p * CC);
    float* dst = out + s * CC;
    #pragma unroll
    for (int i = 0; i < 5; i++) {
        float2 f = upk_h2(src[i]);
        asm volatile("red.global.add.v2.f32 [%0], {%1,%2};"
                     :: "l"(dst + i * 2), "f"(v * f.x), "f"(v * f.y) : "memory");
    }
}

// ============================ launch ============================
extern "C" void kernel_launch(void* const* d_in, const int* in_sizes, int n_in,
                              void* d_out, int out_size) {
    const float* emb = (const float*)d_in[0];
    const float* w1  = (const float*)d_in[1];
    const float* b1  = (const float*)d_in[2];
    const float* w2  = (const float*)d_in[3];
    const float* b2  = (const float*)d_in[4];
    const float* ev  = (const float*)d_in[5];
    const int*   es  = (const int*)d_in[6];
    const int*   ep  = (const int*)d_in[7];
    const int*   eo  = (const int*)d_in[8];
    float* out = (float*)d_out;
    const int E = in_sizes[5];

    k_prep<<<(NRWP * DD + 255) / 256, 256>>>(w1, b2, out);
    k_gemm1<<<dim3(6, (NN + 127) / 128), 256>>>(emb);
    k_edge1<<<((long long)E * 2 + 255) / 256, 256>>>(ev, es, ep, eo, E);
    k_act<<<(NN * WSZ + 255) / 256, 256>>>(b1);
    k_proj2<<<dim3((NN + 255) / 256, 3), 128>>>(w2);
    k_edge2<<<(E + 255) / 256, 256>>>(ev, es, ep, eo, out, E);
}